// round 4
// baseline (speedup 1.0000x reference)
#include <cuda_runtime.h>
#include <cuda_bf16.h>
#include <cstdint>

#define NNODE 50000
#define HDIM  128
#define GNUM  64
#define EPSBN 1e-5f

// ---------------- device scratch (no allocs allowed) ----------------
__device__ float g_K [NNODE * HDIM];
__device__ float g_Q [NNODE * HDIM];
__device__ float g_V [NNODE * HDIM];
__device__ float g_H0[NNODE * HDIM];
__device__ float g_H1[NNODE * HDIM];
__device__ float g_pool[GNUM * 2 * HDIM];

// ---------------- bf16 split helpers ----------------
__device__ __forceinline__ void split2(float x, float y, uint32_t& hi, uint32_t& lo) {
    __nv_bfloat162 h = __floats2bfloat162_rn(x, y);
    float hx = __bfloat162float(h.x);
    float hy = __bfloat162float(h.y);
    __nv_bfloat162 l = __floats2bfloat162_rn(x - hx, y - hy);
    hi = *(uint32_t*)&h;
    lo = *(uint32_t*)&l;
}

__device__ __forceinline__ void mma_bf16(float c[4], const uint32_t a[4], const uint32_t b[2]) {
    asm volatile(
        "mma.sync.aligned.m16n8k16.row.col.f32.bf16.bf16.f32 "
        "{%0,%1,%2,%3}, {%4,%5,%6,%7}, {%8,%9}, {%0,%1,%2,%3};"
        : "+f"(c[0]), "+f"(c[1]), "+f"(c[2]), "+f"(c[3])
        : "r"(a[0]), "r"(a[1]), "r"(a[2]), "r"(a[3]), "r"(b[0]), "r"(b[1]));
}

// ---------------- bf16x3 tensor-core GEMM with register-staged prefetch ----
// grid = (ceil(N/128), 4 weight-select), 256 threads (8 warps).
// BM=128, BN=128, BK=32. Warp tile 32x64 via m16n8k16, hi/lo split.
#define KP 20   // kpair stride (16 used + 4 pad)
template <bool RELU_IN>
__global__ __launch_bounds__(256) void gemm_bf16x3_kernel(
    const float* __restrict__ X,
    const float* __restrict__ Wk, const float* __restrict__ Wq,
    const float* __restrict__ Wv, const float* __restrict__ Ws,
    const float* __restrict__ bk, const float* __restrict__ bq,
    const float* __restrict__ bv, const float* __restrict__ bs,
    float* __restrict__ oK, float* __restrict__ oQ,
    float* __restrict__ oV, float* __restrict__ oS, int N)
{
    const int sel = blockIdx.y;
    const float* W    = (sel == 0) ? Wk : (sel == 1) ? Wq : (sel == 2) ? Wv : Ws;
    const float* bias = (sel == 0) ? bk : (sel == 1) ? bq : (sel == 2) ? bv : bs;
    float*       out  = (sel == 0) ? oK : (sel == 1) ? oQ : (sel == 2) ? oV : oS;
    const int m0 = blockIdx.x * 128;

    __shared__ uint32_t AsH[128][KP], AsL[128][KP];   // [row][kpair]
    __shared__ uint32_t BsH[128][KP], BsL[128][KP];   // [n][kpair]

    const int tid  = threadIdx.x;
    const int wid  = tid >> 5;
    const int lane = tid & 31;
    const int wm  = wid & 3;        // 0..3 -> 32-row slab
    const int wn  = wid >> 2;       // 0..1 -> 64-col slab
    const int tp  = lane >> 2;      // groupID 0..7
    const int tig = lane & 3;       // 0..3

    float c[2][8][4];
#pragma unroll
    for (int mt = 0; mt < 2; mt++)
#pragma unroll
        for (int nt = 0; nt < 8; nt++)
#pragma unroll
            for (int j = 0; j < 4; j++) c[mt][nt][j] = 0.f;

    float4 pa[4], pb[4];

    auto gload = [&](int k0) {
#pragma unroll
        for (int it = 0; it < 4; it++) {
            const int idx = tid + it * 256;       // 0..1023
            const int row = idx >> 3;
            const int c4  = (idx & 7) * 4;
            const int gm  = m0 + row;
            pa[it] = (gm < N) ? *(const float4*)(X + (long)gm * HDIM + k0 + c4)
                              : make_float4(0.f, 0.f, 0.f, 0.f);
            pb[it] = *(const float4*)(W + (long)row * HDIM + k0 + c4);
        }
    };
    auto sstore = [&]() {
#pragma unroll
        for (int it = 0; it < 4; it++) {
            const int idx = tid + it * 256;
            const int row = idx >> 3;
            const int c4  = (idx & 7) * 4;
            const int kp  = c4 >> 1;
            float4 a = pa[it];
            if (RELU_IN) {
                a.x = fmaxf(a.x, 0.f); a.y = fmaxf(a.y, 0.f);
                a.z = fmaxf(a.z, 0.f); a.w = fmaxf(a.w, 0.f);
            }
            uint32_t h0, l0, h1, l1;
            split2(a.x, a.y, h0, l0);
            split2(a.z, a.w, h1, l1);
            AsH[row][kp] = h0; AsH[row][kp + 1] = h1;
            AsL[row][kp] = l0; AsL[row][kp + 1] = l1;
            const float4 b = pb[it];
            split2(b.x, b.y, h0, l0);
            split2(b.z, b.w, h1, l1);
            BsH[row][kp] = h0; BsH[row][kp + 1] = h1;
            BsL[row][kp] = l0; BsL[row][kp + 1] = l1;
        }
    };

    gload(0);
    for (int k0 = 0; k0 < HDIM; k0 += 32) {
        sstore();
        __syncthreads();
        if (k0 + 32 < HDIM) gload(k0 + 32);   // prefetch next tile during compute

#pragma unroll
        for (int ks = 0; ks < 2; ks++) {          // two k16 steps per BK=32
            const int kb = ks * 8;                // kpair base
            uint32_t ah[2][4], al[2][4];
#pragma unroll
            for (int mt = 0; mt < 2; mt++) {
                const int r = wm * 32 + mt * 16 + tp;
                ah[mt][0] = AsH[r    ][kb + tig];
                ah[mt][1] = AsH[r + 8][kb + tig];
                ah[mt][2] = AsH[r    ][kb + tig + 4];
                ah[mt][3] = AsH[r + 8][kb + tig + 4];
                al[mt][0] = AsL[r    ][kb + tig];
                al[mt][1] = AsL[r + 8][kb + tig];
                al[mt][2] = AsL[r    ][kb + tig + 4];
                al[mt][3] = AsL[r + 8][kb + tig + 4];
            }
            uint32_t bh[8][2], bl[8][2];
#pragma unroll
            for (int nt = 0; nt < 8; nt++) {
                const int col = wn * 64 + nt * 8 + tp;
                bh[nt][0] = BsH[col][kb + tig];
                bh[nt][1] = BsH[col][kb + tig + 4];
                bl[nt][0] = BsL[col][kb + tig];
                bl[nt][1] = BsL[col][kb + tig + 4];
            }
#pragma unroll
            for (int mt = 0; mt < 2; mt++)
#pragma unroll
                for (int nt = 0; nt < 8; nt++) {
                    mma_bf16(c[mt][nt], ah[mt], bl[nt]);   // cross terms
                    mma_bf16(c[mt][nt], al[mt], bh[nt]);
                    mma_bf16(c[mt][nt], ah[mt], bh[nt]);   // main term
                }
        }
        __syncthreads();
    }

    // epilogue: bias add + store
#pragma unroll
    for (int nt = 0; nt < 8; nt++) {
        const int col = wn * 64 + nt * 8 + 2 * tig;
        const float b0 = bias[col];
        const float b1 = bias[col + 1];
#pragma unroll
        for (int mt = 0; mt < 2; mt++) {
            const int r0 = m0 + wm * 32 + mt * 16 + tp;
            const int r1 = r0 + 8;
            if (r0 < N) {
                float2 v = make_float2(c[mt][nt][0] + b0, c[mt][nt][1] + b1);
                *(float2*)(out + (long)r0 * HDIM + col) = v;
            }
            if (r1 < N) {
                float2 v = make_float2(c[mt][nt][2] + b0, c[mt][nt][3] + b1);
                *(float2*)(out + (long)r1 * HDIM + col) = v;
            }
        }
    }
}

// ---------------- edge kernel: 4 edges per warp, phase-split for MLP -------
// agg[dst] += sigmoid(K[dst]+Q[src]) * V[src]
__global__ __launch_bounds__(256) void edge_kernel(
    const int* __restrict__ ei, int E,
    const float* __restrict__ K, const float* __restrict__ Q,
    const float* __restrict__ V, float* __restrict__ AGG)
{
    const int w    = (blockIdx.x * blockDim.x + threadIdx.x) >> 5;
    const int lane = threadIdx.x & 31;
    const int e0   = w * 4;
    if (e0 >= E) return;

    // phase 0: indices (vectorized when possible)
    int s[4], d[4];
    if (e0 + 3 < E && ((E & 3) == 0)) {
        const int4 ss = __ldg((const int4*)(ei + e0));
        const int4 dd = __ldg((const int4*)(ei + E + e0));
        s[0] = ss.x; s[1] = ss.y; s[2] = ss.z; s[3] = ss.w;
        d[0] = dd.x; d[1] = dd.y; d[2] = dd.z; d[3] = dd.w;
    } else {
#pragma unroll
        for (int i = 0; i < 4; i++) {
            const int e = (e0 + i < E) ? e0 + i : e0;
            s[i] = __ldg(ei + e);
            d[i] = __ldg(ei + E + e);
        }
    }

    // phase 1: all gathers issued back-to-back (MLP = 12)
    float4 k4[4], q4[4], v4[4];
#pragma unroll
    for (int i = 0; i < 4; i++) {
        k4[i] = *(const float4*)(K + (long)d[i] * HDIM + lane * 4);
        q4[i] = *(const float4*)(Q + (long)s[i] * HDIM + lane * 4);
        v4[i] = *(const float4*)(V + (long)s[i] * HDIM + lane * 4);
    }

    // phase 2: gate + scatter
#pragma unroll
    for (int i = 0; i < 4; i++) {
        if (e0 + i < E) {
            const float g0 = 1.f / (1.f + __expf(-(k4[i].x + q4[i].x)));
            const float g1 = 1.f / (1.f + __expf(-(k4[i].y + q4[i].y)));
            const float g2 = 1.f / (1.f + __expf(-(k4[i].z + q4[i].z)));
            const float g3 = 1.f / (1.f + __expf(-(k4[i].w + q4[i].w)));
            float* o = AGG + (long)d[i] * HDIM + lane * 4;
            asm volatile("red.global.add.v4.f32 [%0], {%1, %2, %3, %4};"
                         :: "l"(o), "f"(g0 * v4[i].x), "f"(g1 * v4[i].y),
                            "f"(g2 * v4[i].z), "f"(g3 * v4[i].w)
                         : "memory");
        }
    }
}

// ---------------- pooling: batch_index is sorted -> binary search segment ---
__device__ __forceinline__ int lower_bound_i(const int* a, int n, int v) {
    int lo = 0, hi = n;
    while (lo < hi) { int m = (lo + hi) >> 1; if (a[m] < v) lo = m + 1; else hi = m; }
    return lo;
}

// grid (G, 4), 128 threads: 4 row-lanes x 32 cols
__global__ void pool_kernel(const float* __restrict__ H,
                            const int* __restrict__ batch, int N,
                            float* __restrict__ pool)
{
    const int g    = blockIdx.x;
    const int c    = blockIdx.y * 32 + (threadIdx.x & 31);
    const int rloc = threadIdx.x >> 5;          // 0..3
    const int lo = lower_bound_i(batch, N, g);
    const int hi = lower_bound_i(batch, N, g + 1);
    float mx = -3.402823466e38f;
    float sm = 0.f;
    for (int n = lo + rloc; n < hi; n += 4) {
        const float x = H[(long)n * HDIM + c];
        mx = fmaxf(mx, x);
        sm += x;
    }
    __shared__ float smx[4][32], ssm[4][32];
    smx[rloc][threadIdx.x & 31] = mx;
    ssm[rloc][threadIdx.x & 31] = sm;
    __syncthreads();
    if (rloc == 0) {
        const int l = threadIdx.x & 31;
        mx = fmaxf(fmaxf(smx[0][l], smx[1][l]), fmaxf(smx[2][l], smx[3][l]));
        sm = ssm[0][l] + ssm[1][l] + ssm[2][l] + ssm[3][l];
        const int cnt = hi - lo;
        pool[g * (2 * HDIM) + c]        = (cnt > 0) ? mx : 0.f;
        pool[g * (2 * HDIM) + HDIM + c] = sm / fmaxf((float)cnt, 1.f);
    }
}

// ---------------- fused MLP head: single block, 256 threads ----------------
__global__ void head_kernel(const float* __restrict__ pool,
                            const float* __restrict__ W1, const float* __restrict__ b1,
                            const float* __restrict__ g1, const float* __restrict__ be1,
                            const float* __restrict__ W2, const float* __restrict__ b2,
                            const float* __restrict__ g2, const float* __restrict__ be2,
                            const float* __restrict__ W3, const float* __restrict__ b3,
                            float* __restrict__ out)
{
    __shared__ float h1s[GNUM][HDIM];       // 32 KB
    __shared__ float h2s[GNUM][HDIM / 2];   // 16 KB
    const int tid = threadIdx.x;

    // ---- layer 1: pre-BN linear (64x128 dots of 256)
    for (int idx = tid; idx < GNUM * HDIM; idx += 256) {
        const int r = idx >> 7;
        const int c = idx & (HDIM - 1);
        const float* w = W1 + (long)c * (2 * HDIM);
        const float* f = pool + (long)r * (2 * HDIM);
        float acc = b1[c];
#pragma unroll 8
        for (int i = 0; i < 2 * HDIM; i++) acc += f[i] * w[i];
        h1s[r][c] = acc;
    }
    __syncthreads();
    if (tid < HDIM) {   // BN per column + relu
        const int c = tid;
        float m = 0.f;
        for (int r = 0; r < GNUM; r++) m += h1s[r][c];
        m /= GNUM;
        float v = 0.f;
        for (int r = 0; r < GNUM; r++) { float t = h1s[r][c] - m; v += t * t; }
        v /= GNUM;
        const float sc = g1[c] * rsqrtf(v + EPSBN);
        const float bb = be1[c];
        for (int r = 0; r < GNUM; r++)
            h1s[r][c] = fmaxf(sc * (h1s[r][c] - m) + bb, 0.f);
    }
    __syncthreads();

    // ---- layer 2: pre-BN linear (64x64 dots of 128)
    for (int idx = tid; idx < GNUM * (HDIM / 2); idx += 256) {
        const int r = idx >> 6;
        const int c = idx & (HDIM / 2 - 1);
        const float* w = W2 + (long)c * HDIM;
        float acc = b2[c];
#pragma unroll 8
        for (int i = 0; i < HDIM; i++) acc += h1s[r][i] * w[i];
        h2s[r][c] = acc;
    }
    __syncthreads();
    if (tid < HDIM / 2) {   // BN per column + relu
        const int c = tid;
        float m = 0.f;
        for (int r = 0; r < GNUM; r++) m += h2s[r][c];
        m /= GNUM;
        float v = 0.f;
        for (int r = 0; r < GNUM; r++) { float t = h2s[r][c] - m; v += t * t; }
        v /= GNUM;
        const float sc = g2[c] * rsqrtf(v + EPSBN);
        const float bb = be2[c];
        for (int r = 0; r < GNUM; r++)
            h2s[r][c] = fmaxf(sc * (h2s[r][c] - m) + bb, 0.f);
    }
    __syncthreads();

    // ---- layer 3: out[r] = h2[r].W3 + b3
    if (tid < GNUM) {
        float acc = b3[0];
#pragma unroll
        for (int i = 0; i < HDIM / 2; i++) acc += h2s[tid][i] * W3[i];
        out[tid] = acc;
    }
}

// ---------------- launch -----------------
extern "C" void kernel_launch(void* const* d_in, const int* in_sizes, int n_in,
                              void* d_out, int out_size)
{
    const float* x     = (const float*)d_in[0];
    const int*   ei    = (const int*)d_in[1];
    const int*   batch = (const int*)d_in[2];
    const int N = in_sizes[0] / HDIM;
    const int E = in_sizes[1] / 2;

    const float* l0W[4], *l0b[4], *l1W[4], *l1b[4];
    for (int i = 0; i < 4; i++) {
        l0W[i] = (const float*)d_in[3 + 2 * i];
        l0b[i] = (const float*)d_in[4 + 2 * i];
        l1W[i] = (const float*)d_in[11 + 2 * i];
        l1b[i] = (const float*)d_in[12 + 2 * i];
    }
    const float* W1  = (const float*)d_in[19];
    const float* b1  = (const float*)d_in[20];
    const float* g1  = (const float*)d_in[21];
    const float* be1 = (const float*)d_in[22];
    const float* W2  = (const float*)d_in[23];
    const float* b2  = (const float*)d_in[24];
    const float* g2  = (const float*)d_in[25];
    const float* be2 = (const float*)d_in[26];
    const float* W3  = (const float*)d_in[27];
    const float* b3  = (const float*)d_in[28];
    float* out = (float*)d_out;

    float *pK, *pQ, *pV, *pH0, *pH1, *pPool;
    cudaGetSymbolAddress((void**)&pK,  g_K);
    cudaGetSymbolAddress((void**)&pQ,  g_Q);
    cudaGetSymbolAddress((void**)&pV,  g_V);
    cudaGetSymbolAddress((void**)&pH0, g_H0);
    cudaGetSymbolAddress((void**)&pH1, g_H1);
    cudaGetSymbolAddress((void**)&pPool, g_pool);

    const dim3 ggrid((N + 127) / 128, 4);
    const int eblocks = (E + 31) / 32;   // 8 warps/block, 4 edges per warp

    // layer 0
    gemm_bf16x3_kernel<false><<<ggrid, 256>>>(x,
        l0W[0], l0W[1], l0W[2], l0W[3], l0b[0], l0b[1], l0b[2], l0b[3],
        pK, pQ, pV, pH0, N);
    edge_kernel<<<eblocks, 256>>>(ei, E, pK, pQ, pV, pH0);
    // layer 1 (relu on input)
    gemm_bf16x3_kernel<true><<<ggrid, 256>>>(pH0,
        l1W[0], l1W[1], l1W[2], l1W[3], l1b[0], l1b[1], l1b[2], l1b[3],
        pK, pQ, pV, pH1, N);
    edge_kernel<<<eblocks, 256>>>(ei, E, pK, pQ, pV, pH1);
    // pooling + fused head
    pool_kernel<<<dim3(GNUM, 4), 128>>>(pH1, batch, N, pPool);
    head_kernel<<<1, 256>>>(pPool, W1, b1, g1, be1, W2, b2, g2, be2, W3, b3, out);
}

// round 5
// speedup vs baseline: 1.0304x; 1.0304x over previous
#include <cuda_runtime.h>
#include <cuda_bf16.h>
#include <cstdint>

#define NNODE 50000
#define HDIM  128
#define GNUM  64
#define EPSBN 1e-5f

// ---------------- device scratch (no allocs allowed) ----------------
__device__ float g_K [NNODE * HDIM];
__device__ float g_Q [NNODE * HDIM];
__device__ float g_V [NNODE * HDIM];
__device__ float g_H0[NNODE * HDIM];
__device__ float g_H1[NNODE * HDIM];
__device__ float g_pool[GNUM * 2 * HDIM];

// ---------------- bf16 split helpers ----------------
__device__ __forceinline__ void split2(float x, float y, uint32_t& hi, uint32_t& lo) {
    __nv_bfloat162 h = __floats2bfloat162_rn(x, y);
    float hx = __bfloat162float(h.x);
    float hy = __bfloat162float(h.y);
    __nv_bfloat162 l = __floats2bfloat162_rn(x - hx, y - hy);
    hi = *(uint32_t*)&h;
    lo = *(uint32_t*)&l;
}

__device__ __forceinline__ void mma_bf16(float c[4], const uint32_t a[4], const uint32_t b[2]) {
    asm volatile(
        "mma.sync.aligned.m16n8k16.row.col.f32.bf16.bf16.f32 "
        "{%0,%1,%2,%3}, {%4,%5,%6,%7}, {%8,%9}, {%0,%1,%2,%3};"
        : "+f"(c[0]), "+f"(c[1]), "+f"(c[2]), "+f"(c[3])
        : "r"(a[0]), "r"(a[1]), "r"(a[2]), "r"(a[3]), "r"(b[0]), "r"(b[1]));
}

// ---------------- bf16x3 tensor-core GEMM (R3-proven, single-buffered) -----
// grid = (ceil(N/128), 4 weight-select), 256 threads (8 warps).
// BM=128, BN=128, BK=32. Warp tile 32x64 via m16n8k16, hi/lo split.
#define KP 20   // kpair stride (16 used + 4 pad)
template <bool RELU_IN>
__global__ __launch_bounds__(256) void gemm_bf16x3_kernel(
    const float* __restrict__ X,
    const float* __restrict__ Wk, const float* __restrict__ Wq,
    const float* __restrict__ Wv, const float* __restrict__ Ws,
    const float* __restrict__ bk, const float* __restrict__ bq,
    const float* __restrict__ bv, const float* __restrict__ bs,
    float* __restrict__ oK, float* __restrict__ oQ,
    float* __restrict__ oV, float* __restrict__ oS, int N)
{
    const int sel = blockIdx.y;
    const float* W    = (sel == 0) ? Wk : (sel == 1) ? Wq : (sel == 2) ? Wv : Ws;
    const float* bias = (sel == 0) ? bk : (sel == 1) ? bq : (sel == 2) ? bv : bs;
    float*       out  = (sel == 0) ? oK : (sel == 1) ? oQ : (sel == 2) ? oV : oS;
    const int m0 = blockIdx.x * 128;

    __shared__ uint32_t AsH[128][KP], AsL[128][KP];   // [row][kpair]
    __shared__ uint32_t BsH[128][KP], BsL[128][KP];   // [n][kpair]

    const int tid  = threadIdx.x;
    const int wid  = tid >> 5;
    const int lane = tid & 31;
    const int wm  = wid & 3;        // 0..3 -> 32-row slab
    const int wn  = wid >> 2;       // 0..1 -> 64-col slab
    const int tp  = lane >> 2;      // groupID 0..7
    const int tig = lane & 3;       // 0..3

    float c[2][8][4];
#pragma unroll
    for (int mt = 0; mt < 2; mt++)
#pragma unroll
        for (int nt = 0; nt < 8; nt++)
#pragma unroll
            for (int j = 0; j < 4; j++) c[mt][nt][j] = 0.f;

    for (int k0 = 0; k0 < HDIM; k0 += 32) {
        // ---- load + split A tile: X[m0:m0+128][k0:k0+32] ----
#pragma unroll
        for (int it = 0; it < 4; it++) {
            const int idx = tid + it * 256;       // 0..1023
            const int row = idx >> 3;
            const int c4  = (idx & 7) * 4;        // k offset in tile
            const int gm  = m0 + row;
            float4 a = make_float4(0.f, 0.f, 0.f, 0.f);
            if (gm < N) a = *(const float4*)(X + (long)gm * HDIM + k0 + c4);
            if (RELU_IN) {
                a.x = fmaxf(a.x, 0.f); a.y = fmaxf(a.y, 0.f);
                a.z = fmaxf(a.z, 0.f); a.w = fmaxf(a.w, 0.f);
            }
            uint32_t h0, l0, h1, l1;
            split2(a.x, a.y, h0, l0);
            split2(a.z, a.w, h1, l1);
            const int kp = c4 >> 1;
            AsH[row][kp] = h0; AsH[row][kp + 1] = h1;
            AsL[row][kp] = l0; AsL[row][kp + 1] = l1;
        }
        // ---- load + split B tile: W[n][k0:k0+32] ----
#pragma unroll
        for (int it = 0; it < 4; it++) {
            const int idx = tid + it * 256;
            const int n   = idx >> 3;
            const int c4  = (idx & 7) * 4;
            const float4 b = *(const float4*)(W + (long)n * HDIM + k0 + c4);
            uint32_t h0, l0, h1, l1;
            split2(b.x, b.y, h0, l0);
            split2(b.z, b.w, h1, l1);
            const int kp = c4 >> 1;
            BsH[n][kp] = h0; BsH[n][kp + 1] = h1;
            BsL[n][kp] = l0; BsL[n][kp + 1] = l1;
        }
        __syncthreads();

#pragma unroll
        for (int ks = 0; ks < 2; ks++) {          // two k16 steps per BK=32
            const int kb = ks * 8;                // kpair base
            uint32_t ah[2][4], al[2][4];
#pragma unroll
            for (int mt = 0; mt < 2; mt++) {
                const int r = wm * 32 + mt * 16 + tp;
                ah[mt][0] = AsH[r    ][kb + tig];
                ah[mt][1] = AsH[r + 8][kb + tig];
                ah[mt][2] = AsH[r    ][kb + tig + 4];
                ah[mt][3] = AsH[r + 8][kb + tig + 4];
                al[mt][0] = AsL[r    ][kb + tig];
                al[mt][1] = AsL[r + 8][kb + tig];
                al[mt][2] = AsL[r    ][kb + tig + 4];
                al[mt][3] = AsL[r + 8][kb + tig + 4];
            }
            uint32_t bh[8][2], bl[8][2];
#pragma unroll
            for (int nt = 0; nt < 8; nt++) {
                const int col = wn * 64 + nt * 8 + tp;
                bh[nt][0] = BsH[col][kb + tig];
                bh[nt][1] = BsH[col][kb + tig + 4];
                bl[nt][0] = BsL[col][kb + tig];
                bl[nt][1] = BsL[col][kb + tig + 4];
            }
#pragma unroll
            for (int mt = 0; mt < 2; mt++)
#pragma unroll
                for (int nt = 0; nt < 8; nt++) {
                    mma_bf16(c[mt][nt], ah[mt], bl[nt]);   // cross terms
                    mma_bf16(c[mt][nt], al[mt], bh[nt]);
                    mma_bf16(c[mt][nt], ah[mt], bh[nt]);   // main term
                }
        }
        __syncthreads();
    }

    // epilogue: bias add + store
#pragma unroll
    for (int nt = 0; nt < 8; nt++) {
        const int col = wn * 64 + nt * 8 + 2 * tig;
        const float b0 = bias[col];
        const float b1 = bias[col + 1];
#pragma unroll
        for (int mt = 0; mt < 2; mt++) {
            const int r0 = m0 + wm * 32 + mt * 16 + tp;
            const int r1 = r0 + 8;
            if (r0 < N) {
                float2 v = make_float2(c[mt][nt][0] + b0, c[mt][nt][1] + b1);
                *(float2*)(out + (long)r0 * HDIM + col) = v;
            }
            if (r1 < N) {
                float2 v = make_float2(c[mt][nt][2] + b0, c[mt][nt][3] + b1);
                *(float2*)(out + (long)r1 * HDIM + col) = v;
            }
        }
    }
}

// ---------------- edge kernel: 2 edges per warp, phase-split ---------------
// agg[dst] += sigmoid(K[dst]+Q[src]) * V[src]
__global__ __launch_bounds__(256) void edge_kernel(
    const int* __restrict__ ei, int E,
    const float* __restrict__ K, const float* __restrict__ Q,
    const float* __restrict__ V, float* __restrict__ AGG)
{
    const int w    = (blockIdx.x * blockDim.x + threadIdx.x) >> 5;
    const int lane = threadIdx.x & 31;
    const int e0   = w * 2;
    if (e0 >= E) return;
    const int e1   = (e0 + 1 < E) ? e0 + 1 : e0;

    // phase 0: indices
    const int s0 = __ldg(ei + e0);
    const int s1 = __ldg(ei + e1);
    const int d0 = __ldg(ei + E + e0);
    const int d1 = __ldg(ei + E + e1);

    // phase 1: all 6 gathers back-to-back (MLP = 6)
    const float4 k0 = *(const float4*)(K + (long)d0 * HDIM + lane * 4);
    const float4 q0 = *(const float4*)(Q + (long)s0 * HDIM + lane * 4);
    const float4 v0 = *(const float4*)(V + (long)s0 * HDIM + lane * 4);
    const float4 k1 = *(const float4*)(K + (long)d1 * HDIM + lane * 4);
    const float4 q1 = *(const float4*)(Q + (long)s1 * HDIM + lane * 4);
    const float4 v1 = *(const float4*)(V + (long)s1 * HDIM + lane * 4);

    // phase 2: gate + scatter
    {
        const float g0 = 1.f / (1.f + __expf(-(k0.x + q0.x)));
        const float g1 = 1.f / (1.f + __expf(-(k0.y + q0.y)));
        const float g2 = 1.f / (1.f + __expf(-(k0.z + q0.z)));
        const float g3 = 1.f / (1.f + __expf(-(k0.w + q0.w)));
        float* o = AGG + (long)d0 * HDIM + lane * 4;
        asm volatile("red.global.add.v4.f32 [%0], {%1, %2, %3, %4};"
                     :: "l"(o), "f"(g0 * v0.x), "f"(g1 * v0.y),
                        "f"(g2 * v0.z), "f"(g3 * v0.w)
                     : "memory");
    }
    if (e0 + 1 < E) {
        const float g0 = 1.f / (1.f + __expf(-(k1.x + q1.x)));
        const float g1 = 1.f / (1.f + __expf(-(k1.y + q1.y)));
        const float g2 = 1.f / (1.f + __expf(-(k1.z + q1.z)));
        const float g3 = 1.f / (1.f + __expf(-(k1.w + q1.w)));
        float* o = AGG + (long)d1 * HDIM + lane * 4;
        asm volatile("red.global.add.v4.f32 [%0], {%1, %2, %3, %4};"
                     :: "l"(o), "f"(g0 * v1.x), "f"(g1 * v1.y),
                        "f"(g2 * v1.z), "f"(g3 * v1.w)
                     : "memory");
    }
}

// ---------------- pooling: batch_index is sorted -> binary search segment ---
__device__ __forceinline__ int lower_bound_i(const int* a, int n, int v) {
    int lo = 0, hi = n;
    while (lo < hi) { int m = (lo + hi) >> 1; if (a[m] < v) lo = m + 1; else hi = m; }
    return lo;
}

// grid (G, 4), 128 threads: 4 row-lanes x 32 cols
__global__ void pool_kernel(const float* __restrict__ H,
                            const int* __restrict__ batch, int N,
                            float* __restrict__ pool)
{
    const int g    = blockIdx.x;
    const int c    = blockIdx.y * 32 + (threadIdx.x & 31);
    const int rloc = threadIdx.x >> 5;          // 0..3
    const int lo = lower_bound_i(batch, N, g);
    const int hi = lower_bound_i(batch, N, g + 1);
    float mx = -3.402823466e38f;
    float sm = 0.f;
    for (int n = lo + rloc; n < hi; n += 4) {
        const float x = H[(long)n * HDIM + c];
        mx = fmaxf(mx, x);
        sm += x;
    }
    __shared__ float smx[4][32], ssm[4][32];
    smx[rloc][threadIdx.x & 31] = mx;
    ssm[rloc][threadIdx.x & 31] = sm;
    __syncthreads();
    if (rloc == 0) {
        const int l = threadIdx.x & 31;
        mx = fmaxf(fmaxf(smx[0][l], smx[1][l]), fmaxf(smx[2][l], smx[3][l]));
        sm = ssm[0][l] + ssm[1][l] + ssm[2][l] + ssm[3][l];
        const int cnt = hi - lo;
        pool[g * (2 * HDIM) + c]        = (cnt > 0) ? mx : 0.f;
        pool[g * (2 * HDIM) + HDIM + c] = sm / fmaxf((float)cnt, 1.f);
    }
}

// ---------------- fused MLP head: single block, 256 threads ----------------
__global__ void head_kernel(const float* __restrict__ pool,
                            const float* __restrict__ W1, const float* __restrict__ b1,
                            const float* __restrict__ g1, const float* __restrict__ be1,
                            const float* __restrict__ W2, const float* __restrict__ b2,
                            const float* __restrict__ g2, const float* __restrict__ be2,
                            const float* __restrict__ W3, const float* __restrict__ b3,
                            float* __restrict__ out)
{
    __shared__ float h1s[GNUM][HDIM];       // 32 KB
    __shared__ float h2s[GNUM][HDIM / 2];   // 16 KB
    const int tid = threadIdx.x;

    // ---- layer 1: pre-BN linear (64x128 dots of 256)
    for (int idx = tid; idx < GNUM * HDIM; idx += 256) {
        const int r = idx >> 7;
        const int c = idx & (HDIM - 1);
        const float* w = W1 + (long)c * (2 * HDIM);
        const float* f = pool + (long)r * (2 * HDIM);
        float acc = b1[c];
#pragma unroll 8
        for (int i = 0; i < 2 * HDIM; i++) acc += f[i] * w[i];
        h1s[r][c] = acc;
    }
    __syncthreads();
    if (tid < HDIM) {   // BN per column + relu
        const int c = tid;
        float m = 0.f;
        for (int r = 0; r < GNUM; r++) m += h1s[r][c];
        m /= GNUM;
        float v = 0.f;
        for (int r = 0; r < GNUM; r++) { float t = h1s[r][c] - m; v += t * t; }
        v /= GNUM;
        const float sc = g1[c] * rsqrtf(v + EPSBN);
        const float bb = be1[c];
        for (int r = 0; r < GNUM; r++)
            h1s[r][c] = fmaxf(sc * (h1s[r][c] - m) + bb, 0.f);
    }
    __syncthreads();

    // ---- layer 2: pre-BN linear (64x64 dots of 128)
    for (int idx = tid; idx < GNUM * (HDIM / 2); idx += 256) {
        const int r = idx >> 6;
        const int c = idx & (HDIM / 2 - 1);
        const float* w = W2 + (long)c * HDIM;
        float acc = b2[c];
#pragma unroll 8
        for (int i = 0; i < HDIM; i++) acc += h1s[r][i] * w[i];
        h2s[r][c] = acc;
    }
    __syncthreads();
    if (tid < HDIM / 2) {   // BN per column + relu
        const int c = tid;
        float m = 0.f;
        for (int r = 0; r < GNUM; r++) m += h2s[r][c];
        m /= GNUM;
        float v = 0.f;
        for (int r = 0; r < GNUM; r++) { float t = h2s[r][c] - m; v += t * t; }
        v /= GNUM;
        const float sc = g2[c] * rsqrtf(v + EPSBN);
        const float bb = be2[c];
        for (int r = 0; r < GNUM; r++)
            h2s[r][c] = fmaxf(sc * (h2s[r][c] - m) + bb, 0.f);
    }
    __syncthreads();

    // ---- layer 3: out[r] = h2[r].W3 + b3
    if (tid < GNUM) {
        float acc = b3[0];
#pragma unroll
        for (int i = 0; i < HDIM / 2; i++) acc += h2s[tid][i] * W3[i];
        out[tid] = acc;
    }
}

// ---------------- launch -----------------
extern "C" void kernel_launch(void* const* d_in, const int* in_sizes, int n_in,
                              void* d_out, int out_size)
{
    const float* x     = (const float*)d_in[0];
    const int*   ei    = (const int*)d_in[1];
    const int*   batch = (const int*)d_in[2];
    const int N = in_sizes[0] / HDIM;
    const int E = in_sizes[1] / 2;

    const float* l0W[4], *l0b[4], *l1W[4], *l1b[4];
    for (int i = 0; i < 4; i++) {
        l0W[i] = (const float*)d_in[3 + 2 * i];
        l0b[i] = (const float*)d_in[4 + 2 * i];
        l1W[i] = (const float*)d_in[11 + 2 * i];
        l1b[i] = (const float*)d_in[12 + 2 * i];
    }
    const float* W1  = (const float*)d_in[19];
    const float* b1  = (const float*)d_in[20];
    const float* g1  = (const float*)d_in[21];
    const float* be1 = (const float*)d_in[22];
    const float* W2  = (const float*)d_in[23];
    const float* b2  = (const float*)d_in[24];
    const float* g2  = (const float*)d_in[25];
    const float* be2 = (const float*)d_in[26];
    const float* W3  = (const float*)d_in[27];
    const float* b3  = (const float*)d_in[28];
    float* out = (float*)d_out;

    float *pK, *pQ, *pV, *pH0, *pH1, *pPool;
    cudaGetSymbolAddress((void**)&pK,  g_K);
    cudaGetSymbolAddress((void**)&pQ,  g_Q);
    cudaGetSymbolAddress((void**)&pV,  g_V);
    cudaGetSymbolAddress((void**)&pH0, g_H0);
    cudaGetSymbolAddress((void**)&pH1, g_H1);
    cudaGetSymbolAddress((void**)&pPool, g_pool);

    const dim3 ggrid((N + 127) / 128, 4);
    const int eblocks = (E + 15) / 16;   // 8 warps/block, 2 edges per warp

    // layer 0
    gemm_bf16x3_kernel<false><<<ggrid, 256>>>(x,
        l0W[0], l0W[1], l0W[2], l0W[3], l0b[0], l0b[1], l0b[2], l0b[3],
        pK, pQ, pV, pH0, N);
    edge_kernel<<<eblocks, 256>>>(ei, E, pK, pQ, pV, pH0);
    // layer 1 (relu on input)
    gemm_bf16x3_kernel<true><<<ggrid, 256>>>(pH0,
        l1W[0], l1W[1], l1W[2], l1W[3], l1b[0], l1b[1], l1b[2], l1b[3],
        pK, pQ, pV, pH1, N);
    edge_kernel<<<eblocks, 256>>>(ei, E, pK, pQ, pV, pH1);
    // pooling + fused head
    pool_kernel<<<dim3(GNUM, 4), 128>>>(pH1, batch, N, pPool);
    head_kernel<<<1, 256>>>(pPool, W1, b1, g1, be1, W2, b2, g2, be2, W3, b3, out);
}

// round 6
// speedup vs baseline: 4.3095x; 4.1824x over previous
#include <cuda_runtime.h>
#include <cuda_bf16.h>
#include <cstdint>

#define NNODE 50000
#define HDIM  128
#define GNUM  64
#define EPSBN 1e-5f

// ---------------- device scratch (no allocs allowed) ----------------
__device__ float g_K [NNODE * HDIM];
__device__ float g_Q [NNODE * HDIM];
__device__ float g_V [NNODE * HDIM];
__device__ float g_H0[NNODE * HDIM];
__device__ float g_H1[NNODE * HDIM];
__device__ float g_pool[GNUM * 2 * HDIM];
__device__ float g_h1m[GNUM * HDIM];
__device__ float g_h2m[GNUM * (HDIM / 2)];

// ---------------- bf16 split helpers ----------------
__device__ __forceinline__ void split2(float x, float y, uint32_t& hi, uint32_t& lo) {
    __nv_bfloat162 h = __floats2bfloat162_rn(x, y);
    float hx = __bfloat162float(h.x);
    float hy = __bfloat162float(h.y);
    __nv_bfloat162 l = __floats2bfloat162_rn(x - hx, y - hy);
    hi = *(uint32_t*)&h;
    lo = *(uint32_t*)&l;
}

__device__ __forceinline__ void mma_bf16(float c[4], const uint32_t a[4], const uint32_t b[2]) {
    asm volatile(
        "mma.sync.aligned.m16n8k16.row.col.f32.bf16.bf16.f32 "
        "{%0,%1,%2,%3}, {%4,%5,%6,%7}, {%8,%9}, {%0,%1,%2,%3};"
        : "+f"(c[0]), "+f"(c[1]), "+f"(c[2]), "+f"(c[3])
        : "r"(a[0]), "r"(a[1]), "r"(a[2]), "r"(a[3]), "r"(b[0]), "r"(b[1]));
}

// ---------------- bf16x3 tensor-core GEMM (R3-proven, single-buffered) -----
// grid = (ceil(N/128), 4 weight-select), 256 threads (8 warps).
// BM=128, BN=128, BK=32. Warp tile 32x64 via m16n8k16, hi/lo split.
#define KP 20   // kpair stride (16 used + 4 pad)
template <bool RELU_IN>
__global__ __launch_bounds__(256) void gemm_bf16x3_kernel(
    const float* __restrict__ X,
    const float* __restrict__ Wk, const float* __restrict__ Wq,
    const float* __restrict__ Wv, const float* __restrict__ Ws,
    const float* __restrict__ bk, const float* __restrict__ bq,
    const float* __restrict__ bv, const float* __restrict__ bs,
    float* __restrict__ oK, float* __restrict__ oQ,
    float* __restrict__ oV, float* __restrict__ oS, int N)
{
    const int sel = blockIdx.y;
    const float* W    = (sel == 0) ? Wk : (sel == 1) ? Wq : (sel == 2) ? Wv : Ws;
    const float* bias = (sel == 0) ? bk : (sel == 1) ? bq : (sel == 2) ? bv : bs;
    float*       out  = (sel == 0) ? oK : (sel == 1) ? oQ : (sel == 2) ? oV : oS;
    const int m0 = blockIdx.x * 128;

    __shared__ uint32_t AsH[128][KP], AsL[128][KP];   // [row][kpair]
    __shared__ uint32_t BsH[128][KP], BsL[128][KP];   // [n][kpair]

    const int tid  = threadIdx.x;
    const int wid  = tid >> 5;
    const int lane = tid & 31;
    const int wm  = wid & 3;        // 0..3 -> 32-row slab
    const int wn  = wid >> 2;       // 0..1 -> 64-col slab
    const int tp  = lane >> 2;      // groupID 0..7
    const int tig = lane & 3;       // 0..3

    float c[2][8][4];
#pragma unroll
    for (int mt = 0; mt < 2; mt++)
#pragma unroll
        for (int nt = 0; nt < 8; nt++)
#pragma unroll
            for (int j = 0; j < 4; j++) c[mt][nt][j] = 0.f;

    for (int k0 = 0; k0 < HDIM; k0 += 32) {
        // ---- load + split A tile: X[m0:m0+128][k0:k0+32] ----
#pragma unroll
        for (int it = 0; it < 4; it++) {
            const int idx = tid + it * 256;       // 0..1023
            const int row = idx >> 3;
            const int c4  = (idx & 7) * 4;        // k offset in tile
            const int gm  = m0 + row;
            float4 a = make_float4(0.f, 0.f, 0.f, 0.f);
            if (gm < N) a = *(const float4*)(X + (long)gm * HDIM + k0 + c4);
            if (RELU_IN) {
                a.x = fmaxf(a.x, 0.f); a.y = fmaxf(a.y, 0.f);
                a.z = fmaxf(a.z, 0.f); a.w = fmaxf(a.w, 0.f);
            }
            uint32_t h0, l0, h1, l1;
            split2(a.x, a.y, h0, l0);
            split2(a.z, a.w, h1, l1);
            const int kp = c4 >> 1;
            AsH[row][kp] = h0; AsH[row][kp + 1] = h1;
            AsL[row][kp] = l0; AsL[row][kp + 1] = l1;
        }
        // ---- load + split B tile: W[n][k0:k0+32] ----
#pragma unroll
        for (int it = 0; it < 4; it++) {
            const int idx = tid + it * 256;
            const int n   = idx >> 3;
            const int c4  = (idx & 7) * 4;
            const float4 b = *(const float4*)(W + (long)n * HDIM + k0 + c4);
            uint32_t h0, l0, h1, l1;
            split2(b.x, b.y, h0, l0);
            split2(b.z, b.w, h1, l1);
            const int kp = c4 >> 1;
            BsH[n][kp] = h0; BsH[n][kp + 1] = h1;
            BsL[n][kp] = l0; BsL[n][kp + 1] = l1;
        }
        __syncthreads();

#pragma unroll
        for (int ks = 0; ks < 2; ks++) {          // two k16 steps per BK=32
            const int kb = ks * 8;                // kpair base
            uint32_t ah[2][4], al[2][4];
#pragma unroll
            for (int mt = 0; mt < 2; mt++) {
                const int r = wm * 32 + mt * 16 + tp;
                ah[mt][0] = AsH[r    ][kb + tig];
                ah[mt][1] = AsH[r + 8][kb + tig];
                ah[mt][2] = AsH[r    ][kb + tig + 4];
                ah[mt][3] = AsH[r + 8][kb + tig + 4];
                al[mt][0] = AsL[r    ][kb + tig];
                al[mt][1] = AsL[r + 8][kb + tig];
                al[mt][2] = AsL[r    ][kb + tig + 4];
                al[mt][3] = AsL[r + 8][kb + tig + 4];
            }
            uint32_t bh[8][2], bl[8][2];
#pragma unroll
            for (int nt = 0; nt < 8; nt++) {
                const int col = wn * 64 + nt * 8 + tp;
                bh[nt][0] = BsH[col][kb + tig];
                bh[nt][1] = BsH[col][kb + tig + 4];
                bl[nt][0] = BsL[col][kb + tig];
                bl[nt][1] = BsL[col][kb + tig + 4];
            }
#pragma unroll
            for (int mt = 0; mt < 2; mt++)
#pragma unroll
                for (int nt = 0; nt < 8; nt++) {
                    mma_bf16(c[mt][nt], ah[mt], bl[nt]);   // cross terms
                    mma_bf16(c[mt][nt], al[mt], bh[nt]);
                    mma_bf16(c[mt][nt], ah[mt], bh[nt]);   // main term
                }
        }
        __syncthreads();
    }

    // epilogue: bias add + store
#pragma unroll
    for (int nt = 0; nt < 8; nt++) {
        const int col = wn * 64 + nt * 8 + 2 * tig;
        const float b0 = bias[col];
        const float b1 = bias[col + 1];
#pragma unroll
        for (int mt = 0; mt < 2; mt++) {
            const int r0 = m0 + wm * 32 + mt * 16 + tp;
            const int r1 = r0 + 8;
            if (r0 < N) {
                float2 v = make_float2(c[mt][nt][0] + b0, c[mt][nt][1] + b1);
                *(float2*)(out + (long)r0 * HDIM + col) = v;
            }
            if (r1 < N) {
                float2 v = make_float2(c[mt][nt][2] + b0, c[mt][nt][3] + b1);
                *(float2*)(out + (long)r1 * HDIM + col) = v;
            }
        }
    }
}

// ---------------- edge kernel: 2 edges per warp, phase-split (R5-proven) ---
// agg[dst] += sigmoid(K[dst]+Q[src]) * V[src]
__global__ __launch_bounds__(256) void edge_kernel(
    const int* __restrict__ ei, int E,
    const float* __restrict__ K, const float* __restrict__ Q,
    const float* __restrict__ V, float* __restrict__ AGG)
{
    const int w    = (blockIdx.x * blockDim.x + threadIdx.x) >> 5;
    const int lane = threadIdx.x & 31;
    const int e0   = w * 2;
    if (e0 >= E) return;
    const int e1   = (e0 + 1 < E) ? e0 + 1 : e0;

    // phase 0: indices
    const int s0 = __ldg(ei + e0);
    const int s1 = __ldg(ei + e1);
    const int d0 = __ldg(ei + E + e0);
    const int d1 = __ldg(ei + E + e1);

    // phase 1: all 6 gathers back-to-back (MLP = 6)
    const float4 k0 = *(const float4*)(K + (long)d0 * HDIM + lane * 4);
    const float4 q0 = *(const float4*)(Q + (long)s0 * HDIM + lane * 4);
    const float4 v0 = *(const float4*)(V + (long)s0 * HDIM + lane * 4);
    const float4 k1 = *(const float4*)(K + (long)d1 * HDIM + lane * 4);
    const float4 q1 = *(const float4*)(Q + (long)s1 * HDIM + lane * 4);
    const float4 v1 = *(const float4*)(V + (long)s1 * HDIM + lane * 4);

    // phase 2: gate + scatter
    {
        const float g0 = 1.f / (1.f + __expf(-(k0.x + q0.x)));
        const float g1 = 1.f / (1.f + __expf(-(k0.y + q0.y)));
        const float g2 = 1.f / (1.f + __expf(-(k0.z + q0.z)));
        const float g3 = 1.f / (1.f + __expf(-(k0.w + q0.w)));
        float* o = AGG + (long)d0 * HDIM + lane * 4;
        asm volatile("red.global.add.v4.f32 [%0], {%1, %2, %3, %4};"
                     :: "l"(o), "f"(g0 * v0.x), "f"(g1 * v0.y),
                        "f"(g2 * v0.z), "f"(g3 * v0.w)
                     : "memory");
    }
    if (e0 + 1 < E) {
        const float g0 = 1.f / (1.f + __expf(-(k1.x + q1.x)));
        const float g1 = 1.f / (1.f + __expf(-(k1.y + q1.y)));
        const float g2 = 1.f / (1.f + __expf(-(k1.z + q1.z)));
        const float g3 = 1.f / (1.f + __expf(-(k1.w + q1.w)));
        float* o = AGG + (long)d1 * HDIM + lane * 4;
        asm volatile("red.global.add.v4.f32 [%0], {%1, %2, %3, %4};"
                     :: "l"(o), "f"(g0 * v1.x), "f"(g1 * v1.y),
                        "f"(g2 * v1.z), "f"(g3 * v1.w)
                     : "memory");
    }
}

// ---------------- pooling: batch_index is sorted -> binary search segment ---
__device__ __forceinline__ int lower_bound_i(const int* a, int n, int v) {
    int lo = 0, hi = n;
    while (lo < hi) { int m = (lo + hi) >> 1; if (a[m] < v) lo = m + 1; else hi = m; }
    return lo;
}

// grid (G, 4), 128 threads: 4 row-lanes x 32 cols
__global__ void pool_kernel(const float* __restrict__ H,
                            const int* __restrict__ batch, int N,
                            float* __restrict__ pool)
{
    const int g    = blockIdx.x;
    const int c    = blockIdx.y * 32 + (threadIdx.x & 31);
    const int rloc = threadIdx.x >> 5;          // 0..3
    const int lo = lower_bound_i(batch, N, g);
    const int hi = lower_bound_i(batch, N, g + 1);
    float mx = -3.402823466e38f;
    float sm = 0.f;
    for (int n = lo + rloc; n < hi; n += 4) {
        const float x = H[(long)n * HDIM + c];
        mx = fmaxf(mx, x);
        sm += x;
    }
    __shared__ float smx[4][32], ssm[4][32];
    smx[rloc][threadIdx.x & 31] = mx;
    ssm[rloc][threadIdx.x & 31] = sm;
    __syncthreads();
    if (rloc == 0) {
        const int l = threadIdx.x & 31;
        mx = fmaxf(fmaxf(smx[0][l], smx[1][l]), fmaxf(smx[2][l], smx[3][l]));
        sm = ssm[0][l] + ssm[1][l] + ssm[2][l] + ssm[3][l];
        const int cnt = hi - lo;
        pool[g * (2 * HDIM) + c]        = (cnt > 0) ? mx : 0.f;
        pool[g * (2 * HDIM) + HDIM + c] = sm / fmaxf((float)cnt, 1.f);
    }
}

// ---------------- MLP head (R3-proven: many blocks, broadcast weights) -----
__global__ void mlp1_kernel(const float* __restrict__ pool,
                            const float* __restrict__ W1, const float* __restrict__ b1,
                            const float* __restrict__ g1, const float* __restrict__ be1,
                            float* __restrict__ h1)
{
    const int c = blockIdx.x;   // 0..127
    const int r = threadIdx.x;  // 0..63
    float acc = b1[c];
    const float* w = W1 + (long)c * (2 * HDIM);
    const float* f = pool + (long)r * (2 * HDIM);
#pragma unroll 8
    for (int i = 0; i < 2 * HDIM; i++) acc += f[i] * w[i];

    __shared__ float red[GNUM];
    red[r] = acc; __syncthreads();
    float m = 0.f;
    if (r == 0) { for (int i = 0; i < GNUM; i++) m += red[i]; red[0] = m / GNUM; }
    __syncthreads();
    m = red[0]; __syncthreads();
    red[r] = (acc - m) * (acc - m); __syncthreads();
    float v = 0.f;
    if (r == 0) { for (int i = 0; i < GNUM; i++) v += red[i]; red[0] = v / GNUM; }
    __syncthreads();
    v = red[0];
    const float y = g1[c] * (acc - m) * rsqrtf(v + EPSBN) + be1[c];
    h1[(long)r * HDIM + c] = fmaxf(y, 0.f);
}

__global__ void mlp2_kernel(const float* __restrict__ h1,
                            const float* __restrict__ W2, const float* __restrict__ b2,
                            const float* __restrict__ g2, const float* __restrict__ be2,
                            float* __restrict__ h2)
{
    const int c = blockIdx.x;   // 0..63
    const int r = threadIdx.x;  // 0..63
    float acc = b2[c];
    const float* w = W2 + (long)c * HDIM;
    const float* f = h1 + (long)r * HDIM;
#pragma unroll 8
    for (int i = 0; i < HDIM; i++) acc += f[i] * w[i];

    __shared__ float red[GNUM];
    red[r] = acc; __syncthreads();
    float m = 0.f;
    if (r == 0) { for (int i = 0; i < GNUM; i++) m += red[i]; red[0] = m / GNUM; }
    __syncthreads();
    m = red[0]; __syncthreads();
    red[r] = (acc - m) * (acc - m); __syncthreads();
    float v = 0.f;
    if (r == 0) { for (int i = 0; i < GNUM; i++) v += red[i]; red[0] = v / GNUM; }
    __syncthreads();
    v = red[0];
    const float y = g2[c] * (acc - m) * rsqrtf(v + EPSBN) + be2[c];
    h2[(long)r * (HDIM / 2) + c] = fmaxf(y, 0.f);
}

__global__ void mlp3_kernel(const float* __restrict__ h2,
                            const float* __restrict__ W3, const float* __restrict__ b3,
                            float* __restrict__ out)
{
    const int r = threadIdx.x;
    float acc = b3[0];
#pragma unroll
    for (int i = 0; i < HDIM / 2; i++) acc += h2[(long)r * (HDIM / 2) + i] * W3[i];
    out[r] = acc;
}

// ---------------- launch -----------------
extern "C" void kernel_launch(void* const* d_in, const int* in_sizes, int n_in,
                              void* d_out, int out_size)
{
    const float* x     = (const float*)d_in[0];
    const int*   ei    = (const int*)d_in[1];
    const int*   batch = (const int*)d_in[2];
    const int N = in_sizes[0] / HDIM;
    const int E = in_sizes[1] / 2;

    const float* l0W[4], *l0b[4], *l1W[4], *l1b[4];
    for (int i = 0; i < 4; i++) {
        l0W[i] = (const float*)d_in[3 + 2 * i];
        l0b[i] = (const float*)d_in[4 + 2 * i];
        l1W[i] = (const float*)d_in[11 + 2 * i];
        l1b[i] = (const float*)d_in[12 + 2 * i];
    }
    const float* W1  = (const float*)d_in[19];
    const float* b1  = (const float*)d_in[20];
    const float* g1  = (const float*)d_in[21];
    const float* be1 = (const float*)d_in[22];
    const float* W2  = (const float*)d_in[23];
    const float* b2  = (const float*)d_in[24];
    const float* g2  = (const float*)d_in[25];
    const float* be2 = (const float*)d_in[26];
    const float* W3  = (const float*)d_in[27];
    const float* b3  = (const float*)d_in[28];
    float* out = (float*)d_out;

    float *pK, *pQ, *pV, *pH0, *pH1, *pPool, *pM1, *pM2;
    cudaGetSymbolAddress((void**)&pK,  g_K);
    cudaGetSymbolAddress((void**)&pQ,  g_Q);
    cudaGetSymbolAddress((void**)&pV,  g_V);
    cudaGetSymbolAddress((void**)&pH0, g_H0);
    cudaGetSymbolAddress((void**)&pH1, g_H1);
    cudaGetSymbolAddress((void**)&pPool, g_pool);
    cudaGetSymbolAddress((void**)&pM1, g_h1m);
    cudaGetSymbolAddress((void**)&pM2, g_h2m);

    const dim3 ggrid((N + 127) / 128, 4);
    const int eblocks = (E + 15) / 16;   // 8 warps/block, 2 edges per warp

    // layer 0
    gemm_bf16x3_kernel<false><<<ggrid, 256>>>(x,
        l0W[0], l0W[1], l0W[2], l0W[3], l0b[0], l0b[1], l0b[2], l0b[3],
        pK, pQ, pV, pH0, N);
    edge_kernel<<<eblocks, 256>>>(ei, E, pK, pQ, pV, pH0);
    // layer 1 (relu on input)
    gemm_bf16x3_kernel<true><<<ggrid, 256>>>(pH0,
        l1W[0], l1W[1], l1W[2], l1W[3], l1b[0], l1b[1], l1b[2], l1b[3],
        pK, pQ, pV, pH1, N);
    edge_kernel<<<eblocks, 256>>>(ei, E, pK, pQ, pV, pH1);
    // pooling + head (R3-proven)
    pool_kernel<<<dim3(GNUM, 4), 128>>>(pH1, batch, N, pPool);
    mlp1_kernel<<<HDIM, GNUM>>>(pPool, W1, b1, g1, be1, pM1);
    mlp2_kernel<<<HDIM / 2, GNUM>>>(pM1, W2, b2, g2, be2, pM2);
    mlp3_kernel<<<1, GNUM>>>(pM2, W3, b3, out);
}